// round 1
// baseline (speedup 1.0000x reference)
#include <cuda_runtime.h>

// Problem constants
constexpr int D   = 128;
constexpr int M   = 8192;
constexpr int L   = 5;
constexpr int K   = 8;
constexpr int KL  = 4;
constexpr int G   = 4096;

constexpr int TILE = 128;
constexpr int PADM = M + K * TILE;    // 9216  (groups padded to 128-row tiles)
constexpr int NTM  = PADM / TILE;     // 72
constexpr int PADG = G + KL * TILE;   // 4608
constexpr int NTG  = PADG / TILE;     // 36

// ---------------- device scratch (static; no allocation) ----------------
__device__ __align__(16) float g_hA[M * D];
__device__ __align__(16) float g_hB[M * D];
__device__ __align__(16) float g_X [PADM * 2 * D];   // [rows, 256]
__device__ __align__(16) float g_Y1[PADM * 4 * D];   // [rows, 512]
__device__ __align__(16) float g_Y2[PADM * 2 * D];   // [rows, 256]

__device__ int g_perm   [L * PADM];
__device__ int g_tilefid[L * NTM];
__device__ int g_counts [L * K];
__device__ int g_cursor [L * K];
__device__ int g_offs   [L * K];

__device__ int g_permG   [PADG];
__device__ int g_tilefidG[NTG];
__device__ int g_countsG [KL];
__device__ int g_cursorG [KL];
__device__ int g_offsG   [KL];

__device__ __forceinline__ float* bufsel(int code, float* out) {
    switch (code) {
        case 0: return g_X;
        case 1: return g_Y1;
        case 2: return g_Y2;
        case 3: return g_hA;
        case 4: return g_hB;
        default: return out;
    }
}

// ---------------- grouping kernels ----------------
__global__ void k_reset() {
    int t = blockIdx.x * blockDim.x + threadIdx.x;
    if (t < L * PADM) g_perm[t] = -1;
    if (t < PADG)     g_permG[t] = -1;
    if (t < L * NTM)  g_tilefid[t] = -1;
    if (t < NTG)      g_tilefidG[t] = -1;
    if (t < L * K)    { g_counts[t] = 0; g_cursor[t] = 0; }
    if (t < KL)       { g_countsG[t] = 0; g_cursorG[t] = 0; }
}

__global__ void k_count(const int* __restrict__ nf, const int* __restrict__ lf) {
    int t = blockIdx.x * blockDim.x + threadIdx.x;
    if (t < L * M) {
        int l = t / M;
        atomicAdd(&g_counts[l * K + nf[t]], 1);
    } else if (t < L * M + G) {
        atomicAdd(&g_countsG[lf[t - L * M]], 1);
    }
}

__global__ void k_scan() {
    for (int l = 0; l < L; l++) {
        int off = 0;
        for (int k = 0; k < K; k++) {
            g_offs[l * K + k] = off;
            int nt = (g_counts[l * K + k] + TILE - 1) / TILE;
            for (int t = 0; t < nt; t++) g_tilefid[l * NTM + off / TILE + t] = k;
            off += nt * TILE;
        }
    }
    int off = 0;
    for (int k = 0; k < KL; k++) {
        g_offsG[k] = off;
        int nt = (g_countsG[k] + TILE - 1) / TILE;
        for (int t = 0; t < nt; t++) g_tilefidG[off / TILE + t] = k;
        off += nt * TILE;
    }
}

__global__ void k_scatter(const int* __restrict__ nf, const int* __restrict__ lf) {
    int t = blockIdx.x * blockDim.x + threadIdx.x;
    if (t < L * M) {
        int l = t / M, m = t % M;
        int f = nf[t];
        int pos = g_offs[l * K + f] + atomicAdd(&g_cursor[l * K + f], 1);
        g_perm[l * PADM + pos] = m;
    } else if (t < L * M + G) {
        int s = t - L * M;
        int f = lf[s];
        int pos = g_offsG[f] + atomicAdd(&g_cursorG[f], 1);
        g_permG[pos] = s;
    }
}

// ---------------- gather kernels ----------------
__global__ void k_leaf(const int* __restrict__ leaf_ids, const float4* __restrict__ emb) {
    int t = blockIdx.x * blockDim.x + threadIdx.x;
    if (t >= M * (D / 4)) return;
    int m = t >> 5, q = t & 31;              // D/4 = 32 float4 per row
    ((float4*)g_hA)[t] = emb[leaf_ids[m] * 32 + q];
}

// lv in [0, L-1] : entity level (PADM rows, perm = g_perm[lv]); lv == L : logic (PADG rows, permG)
__global__ void k_gather(int lv, const int* __restrict__ li, const int* __restrict__ ri, int hsel) {
    const int nrows = (lv < L) ? PADM : PADG;
    int t = blockIdx.x * blockDim.x + threadIdx.x;
    if (t >= nrows * 64) return;             // 2D/4 = 64 float4 per row
    int r = t >> 6, q = t & 63;
    const int* perm = (lv < L) ? (g_perm + lv * PADM) : g_permG;
    int node = perm[r];
    float4 v = make_float4(0.f, 0.f, 0.f, 0.f);
    if (node >= 0) {
        const float4* h = (const float4*)((hsel == 3) ? g_hA : g_hB);
        int idx = (q < 32) ? (li[node] * 32 + q) : (ri[node] * 32 + (q - 32));
        v = h[idx];
    }
    ((float4*)g_X)[t] = v;
}

// ---------------- grouped SGEMM ----------------
// C[row, col] = A[row, :Kd] @ W[fid][:, col] + bias[fid][col], fid constant per 128-row tile.
// BM=BN=128, BK=16, 256 threads, 8x8 per thread.
template <bool RELU, bool SCATTER>
__global__ __launch_bounds__(256) void k_gemm(
    int lv, int Acode, int Kd, int Nd,
    const float* __restrict__ Wb, const float* __restrict__ bb,
    int Ccode, float* __restrict__ outbuf)
{
    const int fid = (lv < L) ? g_tilefid[lv * NTM + blockIdx.x] : g_tilefidG[blockIdx.x];
    if (fid < 0) return;

    const float* __restrict__ A    = bufsel(Acode, nullptr);
    const float* __restrict__ W    = Wb + (size_t)fid * Kd * Nd;
    const float* __restrict__ bias = bb + fid * Nd;

    const int rowBase = blockIdx.x * 128;
    const int colBase = blockIdx.y * 128;

    __shared__ float As[16][128];
    __shared__ float Bs[16][128];

    const int tid  = threadIdx.x;
    const int aRow = tid >> 2, aCol = (tid & 3) << 2;
    const int bRow = tid >> 5, bCol = (tid & 31) << 2;
    const int m0   = (tid >> 4) << 3, n0 = (tid & 15) << 3;

    const float* Abase = A + (size_t)rowBase * Kd;

    float acc[8][8];
#pragma unroll
    for (int i = 0; i < 8; i++)
#pragma unroll
        for (int j = 0; j < 8; j++) acc[i][j] = 0.f;

    for (int kt = 0; kt < Kd; kt += 16) {
        float4 a0 = *(const float4*)(Abase + (size_t)aRow * Kd + kt + aCol);
        float4 a1 = *(const float4*)(Abase + (size_t)(aRow + 64) * Kd + kt + aCol);
        float4 b0 = *(const float4*)(W + (size_t)(kt + bRow) * Nd + colBase + bCol);
        float4 b1 = *(const float4*)(W + (size_t)(kt + bRow + 8) * Nd + colBase + bCol);

        As[aCol + 0][aRow] = a0.x; As[aCol + 1][aRow] = a0.y;
        As[aCol + 2][aRow] = a0.z; As[aCol + 3][aRow] = a0.w;
        As[aCol + 0][aRow + 64] = a1.x; As[aCol + 1][aRow + 64] = a1.y;
        As[aCol + 2][aRow + 64] = a1.z; As[aCol + 3][aRow + 64] = a1.w;
        *(float4*)&Bs[bRow][bCol]     = b0;
        *(float4*)&Bs[bRow + 8][bCol] = b1;
        __syncthreads();

#pragma unroll
        for (int k = 0; k < 16; k++) {
            float ra[8], rb[8];
#pragma unroll
            for (int i = 0; i < 8; i++) ra[i] = As[k][m0 + i];
#pragma unroll
            for (int j = 0; j < 8; j++) rb[j] = Bs[k][n0 + j];
#pragma unroll
            for (int i = 0; i < 8; i++)
#pragma unroll
                for (int j = 0; j < 8; j++) acc[i][j] += ra[i] * rb[j];
        }
        __syncthreads();
    }

    const int* perm = (lv < L) ? (g_perm + lv * PADM) : g_permG;
    float* Cbase = bufsel(Ccode, outbuf);

#pragma unroll
    for (int i = 0; i < 8; i++) {
        int row = rowBase + m0 + i;
        int dstRow = row;
        if (SCATTER) {
            dstRow = perm[row];
            if (dstRow < 0) continue;
        }
        float* outp = Cbase + (size_t)dstRow * Nd + colBase + n0;
#pragma unroll
        for (int j = 0; j < 8; j++) {
            float v = acc[i][j] + bias[colBase + n0 + j];
            if (RELU) v = fmaxf(v, 0.f);
            outp[j] = v;
        }
    }
}

// ---------------- launch ----------------
extern "C" void kernel_launch(void* const* d_in, const int* in_sizes, int n_in,
                              void* d_out, int out_size)
{
    const int*   leaf_ids = (const int*)d_in[0];
    const int*   left_idx = (const int*)d_in[1];
    const int*   right_idx= (const int*)d_in[2];
    const int*   nf_fid   = (const int*)d_in[3];
    const int*   gt_left  = (const int*)d_in[4];
    const int*   gt_right = (const int*)d_in[5];
    const int*   lf_fid   = (const int*)d_in[6];
    const float* emb      = (const float*)d_in[7];
    const float* W1 = (const float*)d_in[8];
    const float* b1 = (const float*)d_in[9];
    const float* W2 = (const float*)d_in[10];
    const float* b2 = (const float*)d_in[11];
    const float* W3 = (const float*)d_in[12];
    const float* b3 = (const float*)d_in[13];
    const float* Wl1= (const float*)d_in[14];
    const float* bl1= (const float*)d_in[15];
    const float* Wl2= (const float*)d_in[16];
    const float* bl2= (const float*)d_in[17];
    float* out = (float*)d_out;

    // group nodes by fid (device-side counting sort; output is order-invariant)
    k_reset  <<<(L * PADM + 255) / 256, 256>>>();
    k_count  <<<(L * M + G + 255) / 256, 256>>>(nf_fid, lf_fid);
    k_scan   <<<1, 1>>>();
    k_scatter<<<(L * M + G + 255) / 256, 256>>>(nf_fid, lf_fid);

    // leaf embeddings -> g_hA
    k_leaf<<<(M * (D / 4) + 255) / 256, 256>>>(leaf_ids, (const float4*)emb);

    int src = 3, dst = 4;  // 3 = g_hA, 4 = g_hB
    for (int l = 0; l < L; l++) {
        k_gather<<<(PADM * 64 + 255) / 256, 256>>>(l, left_idx + l * M, right_idx + l * M, src);
        dim3 g1(NTM, 4), g2(NTM, 2), g3(NTM, 1);
        k_gemm<true,  false><<<g1, 256>>>(l, 0, 2 * D, 4 * D, W1, b1, 1, nullptr); // X  -> Y1, relu
        k_gemm<true,  false><<<g2, 256>>>(l, 1, 4 * D, 2 * D, W2, b2, 2, nullptr); // Y1 -> Y2, relu
        k_gemm<false, true ><<<g3, 256>>>(l, 2, 2 * D, 1 * D, W3, b3, dst, nullptr); // Y2 -> h_next (scatter)
        int t = src; src = dst; dst = t;
    }

    // logic statements on final h (in buffer `src`)
    k_gather<<<(PADG * 64 + 255) / 256, 256>>>(L, gt_left, gt_right, src);
    dim3 gl1(NTG, 4), gl2(NTG, 1);
    k_gemm<true,  false><<<gl1, 256>>>(L, 0, 2 * D, 4 * D, Wl1, bl1, 1, nullptr);  // X  -> Y1, relu
    k_gemm<false, true ><<<gl2, 256>>>(L, 1, 4 * D, 1 * D, Wl2, bl2, 5, out);      // Y1 -> out (scatter)
}

// round 2
// speedup vs baseline: 1.0853x; 1.0853x over previous
#include <cuda_runtime.h>

// Problem constants
constexpr int D   = 128;
constexpr int M   = 8192;
constexpr int L   = 5;
constexpr int K   = 8;
constexpr int KL  = 4;
constexpr int G   = 4096;

constexpr int TILE = 128;
constexpr int PADM = M + K * TILE;    // 9216  (groups padded to 128-row tiles)
constexpr int NTM  = PADM / TILE;     // 72
constexpr int PADG = G + KL * TILE;   // 4608
constexpr int NTG  = PADG / TILE;     // 36

// ---------------- device scratch (static; no allocation) ----------------
__device__ __align__(16) float g_hA[M * D];
__device__ __align__(16) float g_hB[M * D];
__device__ __align__(16) float g_X [PADM * 2 * D];   // [rows, 256]
__device__ __align__(16) float g_Y1[PADM * 4 * D];   // [rows, 512]
__device__ __align__(16) float g_Y2[PADM * 2 * D];   // [rows, 256]

__device__ int g_perm   [L * PADM];
__device__ int g_tilefid[L * NTM];
__device__ int g_counts [L * K];
__device__ int g_cursor [L * K];
__device__ int g_offs   [L * K];

__device__ int g_permG   [PADG];
__device__ int g_tilefidG[NTG];
__device__ int g_countsG [KL];
__device__ int g_cursorG [KL];
__device__ int g_offsG   [KL];

__device__ __forceinline__ float* bufsel(int code, float* out) {
    switch (code) {
        case 0: return g_X;
        case 1: return g_Y1;
        case 2: return g_Y2;
        case 3: return g_hA;
        case 4: return g_hB;
        default: return out;
    }
}

// ---------------- grouping kernels ----------------
__global__ void k_reset() {
    int t = blockIdx.x * blockDim.x + threadIdx.x;
    if (t < L * PADM) g_perm[t] = -1;
    if (t < PADG)     g_permG[t] = -1;
    if (t < L * NTM)  g_tilefid[t] = -1;
    if (t < NTG)      g_tilefidG[t] = -1;
    if (t < L * K)    { g_counts[t] = 0; g_cursor[t] = 0; }
    if (t < KL)       { g_countsG[t] = 0; g_cursorG[t] = 0; }
}

__global__ void k_count(const int* __restrict__ nf, const int* __restrict__ lf) {
    int t = blockIdx.x * blockDim.x + threadIdx.x;
    if (t < L * M) {
        int l = t / M;
        atomicAdd(&g_counts[l * K + nf[t]], 1);
    } else if (t < L * M + G) {
        atomicAdd(&g_countsG[lf[t - L * M]], 1);
    }
}

__global__ void k_scan() {
    for (int l = 0; l < L; l++) {
        int off = 0;
        for (int k = 0; k < K; k++) {
            g_offs[l * K + k] = off;
            int nt = (g_counts[l * K + k] + TILE - 1) / TILE;
            for (int t = 0; t < nt; t++) g_tilefid[l * NTM + off / TILE + t] = k;
            off += nt * TILE;
        }
    }
    int off = 0;
    for (int k = 0; k < KL; k++) {
        g_offsG[k] = off;
        int nt = (g_countsG[k] + TILE - 1) / TILE;
        for (int t = 0; t < nt; t++) g_tilefidG[off / TILE + t] = k;
        off += nt * TILE;
    }
}

__global__ void k_scatter(const int* __restrict__ nf, const int* __restrict__ lf) {
    int t = blockIdx.x * blockDim.x + threadIdx.x;
    if (t < L * M) {
        int l = t / M, m = t % M;
        int f = nf[t];
        int pos = g_offs[l * K + f] + atomicAdd(&g_cursor[l * K + f], 1);
        g_perm[l * PADM + pos] = m;
    } else if (t < L * M + G) {
        int s = t - L * M;
        int f = lf[s];
        int pos = g_offsG[f] + atomicAdd(&g_cursorG[f], 1);
        g_permG[pos] = s;
    }
}

// ---------------- gather kernels ----------------
__global__ void k_leaf(const int* __restrict__ leaf_ids, const float4* __restrict__ emb) {
    int t = blockIdx.x * blockDim.x + threadIdx.x;
    if (t >= M * (D / 4)) return;
    int m = t >> 5, q = t & 31;              // D/4 = 32 float4 per row
    ((float4*)g_hA)[t] = emb[leaf_ids[m] * 32 + q];
}

// lv in [0, L-1] : entity level (PADM rows, perm = g_perm[lv]); lv == L : logic (PADG rows, permG)
__global__ void k_gather(int lv, const int* __restrict__ li, const int* __restrict__ ri, int hsel) {
    const int nrows = (lv < L) ? PADM : PADG;
    int t = blockIdx.x * blockDim.x + threadIdx.x;
    if (t >= nrows * 64) return;             // 2D/4 = 64 float4 per row
    int r = t >> 6, q = t & 63;
    const int* perm = (lv < L) ? (g_perm + lv * PADM) : g_permG;
    int node = perm[r];
    float4 v = make_float4(0.f, 0.f, 0.f, 0.f);
    if (node >= 0) {
        const float4* h = (const float4*)((hsel == 3) ? g_hA : g_hB);
        int idx = (q < 32) ? (li[node] * 32 + q) : (ri[node] * 32 + (q - 32));
        v = h[idx];
    }
    ((float4*)g_X)[t] = v;
}

// ---------------- grouped SGEMM (packed f32x2 / FFMA2) ----------------
// C[row, col] = A[row, :Kd] @ W[fid][:, col] + bias[fid][col], fid constant per 128-row tile.
// BM=BN=128, BK=16, 128 threads, thread tile 16(m) x 8(n), accumulators packed
// pairwise along m into f32x2 -> 64 fma.rn.f32x2 per thread per k.
template <bool RELU, bool SCATTER>
__global__ __launch_bounds__(128, 2) void k_gemm(
    int lv, int Acode, int Kd, int Nd,
    const float* __restrict__ Wb, const float* __restrict__ bb,
    int Ccode, float* __restrict__ outbuf)
{
    const int fid = (lv < L) ? g_tilefid[lv * NTM + blockIdx.x] : g_tilefidG[blockIdx.x];
    if (fid < 0) return;

    const float* __restrict__ A    = bufsel(Acode, nullptr);
    const float* __restrict__ W    = Wb + (size_t)fid * Kd * Nd;
    const float* __restrict__ bias = bb + fid * Nd;

    const int rowBase = blockIdx.x * 128;
    const int colBase = blockIdx.y * 128;

    __shared__ __align__(16) float As[16][128];
    __shared__ __align__(16) float Bs[16][128];

    const int tid = threadIdx.x;
    const int m0 = (tid >> 4) << 4;      // 0,16,...,112
    const int n0 = (tid & 15) << 3;      // 0,8,...,120

    // global load mapping: each thread owns one A row; B rows strided by 4
    const float* Arow = A + (size_t)(rowBase + tid) * Kd;
    const int bRow = tid >> 5;            // 0..3
    const int bCol = (tid & 31) << 2;     // 0..124 step 4

    unsigned long long acc[8][8];
#pragma unroll
    for (int i = 0; i < 8; i++)
#pragma unroll
        for (int j = 0; j < 8; j++) acc[i][j] = 0ULL;

    float4 pa[4], pb[4];
#pragma unroll
    for (int c = 0; c < 4; c++)
        pa[c] = *(const float4*)(Arow + c * 4);
#pragma unroll
    for (int r = 0; r < 4; r++)
        pb[r] = *(const float4*)(W + (size_t)(bRow + r * 4) * Nd + colBase + bCol);

    for (int kt = 0; kt < Kd; kt += 16) {
        __syncthreads();
#pragma unroll
        for (int c = 0; c < 4; c++) {
            As[c * 4 + 0][tid] = pa[c].x;
            As[c * 4 + 1][tid] = pa[c].y;
            As[c * 4 + 2][tid] = pa[c].z;
            As[c * 4 + 3][tid] = pa[c].w;
        }
#pragma unroll
        for (int r = 0; r < 4; r++)
            *(float4*)&Bs[bRow + r * 4][bCol] = pb[r];
        __syncthreads();

        if (kt + 16 < Kd) {
#pragma unroll
            for (int c = 0; c < 4; c++)
                pa[c] = *(const float4*)(Arow + kt + 16 + c * 4);
#pragma unroll
            for (int r = 0; r < 4; r++)
                pb[r] = *(const float4*)(W + (size_t)(kt + 16 + bRow + r * 4) * Nd + colBase + bCol);
        }

#pragma unroll
        for (int k = 0; k < 16; k++) {
            unsigned long long ra2[8];
            const unsigned long long* a64 = (const unsigned long long*)&As[k][m0];
#pragma unroll
            for (int i = 0; i < 8; i++) ra2[i] = a64[i];

            float rb[8];
            *(float4*)&rb[0] = *(const float4*)&Bs[k][n0];
            *(float4*)&rb[4] = *(const float4*)&Bs[k][n0 + 4];

            unsigned long long rbp[8];
#pragma unroll
            for (int j = 0; j < 8; j++)
                asm("mov.b64 %0, {%1, %1};" : "=l"(rbp[j]) : "r"(__float_as_uint(rb[j])));

#pragma unroll
            for (int i = 0; i < 8; i++)
#pragma unroll
                for (int j = 0; j < 8; j++)
                    asm("fma.rn.f32x2 %0, %1, %2, %0;"
                        : "+l"(acc[i][j]) : "l"(ra2[i]), "l"(rbp[j]));
        }
    }

    const int* perm = (lv < L) ? (g_perm + lv * PADM) : g_permG;
    float* Cbase = bufsel(Ccode, outbuf);

    float bj[8];
#pragma unroll
    for (int j = 0; j < 8; j++) bj[j] = bias[colBase + n0 + j];

#pragma unroll
    for (int i = 0; i < 8; i++) {
#pragma unroll
        for (int s = 0; s < 2; s++) {
            int row = rowBase + m0 + 2 * i + s;
            int dstRow = row;
            if (SCATTER) {
                dstRow = perm[row];
                if (dstRow < 0) continue;
            }
            float* outp = Cbase + (size_t)dstRow * Nd + colBase + n0;
#pragma unroll
            for (int j = 0; j < 8; j++) {
                float2 v = *(float2*)&acc[i][j];
                float val = ((s == 0) ? v.x : v.y) + bj[j];
                if (RELU) val = fmaxf(val, 0.f);
                outp[j] = val;
            }
        }
    }
}

// ---------------- launch ----------------
extern "C" void kernel_launch(void* const* d_in, const int* in_sizes, int n_in,
                              void* d_out, int out_size)
{
    const int*   leaf_ids = (const int*)d_in[0];
    const int*   left_idx = (const int*)d_in[1];
    const int*   right_idx= (const int*)d_in[2];
    const int*   nf_fid   = (const int*)d_in[3];
    const int*   gt_left  = (const int*)d_in[4];
    const int*   gt_right = (const int*)d_in[5];
    const int*   lf_fid   = (const int*)d_in[6];
    const float* emb      = (const float*)d_in[7];
    const float* W1 = (const float*)d_in[8];
    const float* b1 = (const float*)d_in[9];
    const float* W2 = (const float*)d_in[10];
    const float* b2 = (const float*)d_in[11];
    const float* W3 = (const float*)d_in[12];
    const float* b3 = (const float*)d_in[13];
    const float* Wl1= (const float*)d_in[14];
    const float* bl1= (const float*)d_in[15];
    const float* Wl2= (const float*)d_in[16];
    const float* bl2= (const float*)d_in[17];
    float* out = (float*)d_out;

    // group nodes by fid (device-side counting sort; output is order-invariant)
    k_reset  <<<(L * PADM + 255) / 256, 256>>>();
    k_count  <<<(L * M + G + 255) / 256, 256>>>(nf_fid, lf_fid);
    k_scan   <<<1, 1>>>();
    k_scatter<<<(L * M + G + 255) / 256, 256>>>(nf_fid, lf_fid);

    // leaf embeddings -> g_hA
    k_leaf<<<(M * (D / 4) + 255) / 256, 256>>>(leaf_ids, (const float4*)emb);

    int src = 3, dst = 4;  // 3 = g_hA, 4 = g_hB
    for (int l = 0; l < L; l++) {
        k_gather<<<(PADM * 64 + 255) / 256, 256>>>(l, left_idx + l * M, right_idx + l * M, src);
        dim3 g1(NTM, 4), g2(NTM, 2), g3(NTM, 1);
        k_gemm<true,  false><<<g1, 128>>>(l, 0, 2 * D, 4 * D, W1, b1, 1, nullptr); // X  -> Y1, relu
        k_gemm<true,  false><<<g2, 128>>>(l, 1, 4 * D, 2 * D, W2, b2, 2, nullptr); // Y1 -> Y2, relu
        k_gemm<false, true ><<<g3, 128>>>(l, 2, 2 * D, 1 * D, W3, b3, dst, nullptr); // Y2 -> h_next (scatter)
        int t = src; src = dst; dst = t;
    }

    // logic statements on final h (in buffer `src`)
    k_gather<<<(PADG * 64 + 255) / 256, 256>>>(L, gt_left, gt_right, src);
    dim3 gl1(NTG, 4), gl2(NTG, 1);
    k_gemm<true,  false><<<gl1, 128>>>(L, 0, 2 * D, 4 * D, Wl1, bl1, 1, nullptr);  // X  -> Y1, relu
    k_gemm<false, true ><<<gl2, 128>>>(L, 1, 4 * D, 1 * D, Wl2, bl2, 5, out);      // Y1 -> out (scatter)
}

// round 4
// speedup vs baseline: 1.6579x; 1.5276x over previous
#include <cuda_runtime.h>
#include <cuda_bf16.h>
#include <cstdint>

// Problem constants
constexpr int D   = 128;
constexpr int M   = 8192;
constexpr int L   = 5;
constexpr int K   = 8;
constexpr int KL  = 4;
constexpr int G   = 4096;

constexpr int TILE = 128;
constexpr int PADM = M + K * TILE;    // 9216
constexpr int NTM  = PADM / TILE;     // 72
constexpr int PADG = G + KL * TILE;   // 4608
constexpr int NTG  = PADG / TILE;     // 36

// ---------------- device scratch (static; no allocation) ----------------
__device__ __align__(16) float g_hA[M * D];
__device__ __align__(16) float g_hB[M * D];

// Activations pre-split to bf16 hi/lo
__device__ __align__(16) __nv_bfloat16 g_Xhi [PADM * 256];
__device__ __align__(16) __nv_bfloat16 g_Xlo [PADM * 256];
__device__ __align__(16) __nv_bfloat16 g_Y1hi[PADM * 512];
__device__ __align__(16) __nv_bfloat16 g_Y1lo[PADM * 512];
__device__ __align__(16) __nv_bfloat16 g_Y2hi[PADM * 256];
__device__ __align__(16) __nv_bfloat16 g_Y2lo[PADM * 256];

__device__ int g_perm   [L * PADM];
__device__ int g_tilefid[L * NTM];
__device__ int g_counts [L * K];
__device__ int g_cursor [L * K];
__device__ int g_offs   [L * K];

__device__ int g_permG   [PADG];
__device__ int g_tilefidG[NTG];
__device__ int g_countsG [KL];
__device__ int g_cursorG [KL];
__device__ int g_offsG   [KL];

// Weights transposed + split, layout [fid][n][3*Kd] with K segments [hi | lo | hi]
constexpr size_t OFF_W1  = 0;                          // 8*512*768
constexpr size_t OFF_W2  = OFF_W1 + 8ull*512*768;      // 8*256*1536
constexpr size_t OFF_W3  = OFF_W2 + 8ull*256*1536;     // 8*128*768
constexpr size_t OFF_WL1 = OFF_W3 + 8ull*128*768;      // 4*512*768
constexpr size_t OFF_WL2 = OFF_WL1 + 4ull*512*768;     // 4*128*1536
constexpr size_t WTOT    = OFF_WL2 + 4ull*128*1536;    // 9,437,184 halves
__device__ __align__(16) __nv_bfloat16 g_Wt[WTOT];

// ---------------- grouping kernels ----------------
__global__ void k_reset() {
    int t = blockIdx.x * blockDim.x + threadIdx.x;
    if (t < L * PADM) g_perm[t] = -1;
    if (t < PADG)     g_permG[t] = -1;
    if (t < L * NTM)  g_tilefid[t] = -1;
    if (t < NTG)      g_tilefidG[t] = -1;
    if (t < L * K)    { g_counts[t] = 0; g_cursor[t] = 0; }
    if (t < KL)       { g_countsG[t] = 0; g_cursorG[t] = 0; }
}

__global__ void k_count(const int* __restrict__ nf, const int* __restrict__ lf) {
    int t = blockIdx.x * blockDim.x + threadIdx.x;
    if (t < L * M) {
        int l = t / M;
        atomicAdd(&g_counts[l * K + nf[t]], 1);
    } else if (t < L * M + G) {
        atomicAdd(&g_countsG[lf[t - L * M]], 1);
    }
}

__global__ void k_scan() {
    for (int l = 0; l < L; l++) {
        int off = 0;
        for (int k = 0; k < K; k++) {
            g_offs[l * K + k] = off;
            int nt = (g_counts[l * K + k] + TILE - 1) / TILE;
            for (int t = 0; t < nt; t++) g_tilefid[l * NTM + off / TILE + t] = k;
            off += nt * TILE;
        }
    }
    int off = 0;
    for (int k = 0; k < KL; k++) {
        g_offsG[k] = off;
        int nt = (g_countsG[k] + TILE - 1) / TILE;
        for (int t = 0; t < nt; t++) g_tilefidG[off / TILE + t] = k;
        off += nt * TILE;
    }
}

__global__ void k_scatter(const int* __restrict__ nf, const int* __restrict__ lf) {
    int t = blockIdx.x * blockDim.x + threadIdx.x;
    if (t < L * M) {
        int l = t / M, m = t % M;
        int f = nf[t];
        int pos = g_offs[l * K + f] + atomicAdd(&g_cursor[l * K + f], 1);
        g_perm[l * PADM + pos] = m;
    } else if (t < L * M + G) {
        int s = t - L * M;
        int f = lf[s];
        int pos = g_offsG[f] + atomicAdd(&g_cursorG[f], 1);
        g_permG[pos] = s;
    }
}

// ---------------- weight convert: W[f][k][n] fp32 -> g_Wt[f][n][3Kd] = [hi|lo|hi]
__global__ void k_wconv(const float* __restrict__ W, size_t woff, int Kd, int Nd) {
    __shared__ float t[32][33];
    int f = blockIdx.z;
    int n0 = blockIdx.x * 32, k0 = blockIdx.y * 32;
    const float* Wf = W + (size_t)f * Kd * Nd;
    for (int rr = threadIdx.y; rr < 32; rr += 8)
        t[rr][threadIdx.x] = Wf[(size_t)(k0 + rr) * Nd + n0 + threadIdx.x];
    __syncthreads();
    int Keff = 3 * Kd;
    __nv_bfloat16* ob = g_Wt + woff + (size_t)f * Nd * Keff;
    for (int rr = threadIdx.y; rr < 32; rr += 8) {
        float x = t[threadIdx.x][rr];      // W[k0+tx][n0+rr]
        __nv_bfloat16 h = __float2bfloat16(x);
        __nv_bfloat16 l = __float2bfloat16(x - __bfloat162float(h));
        size_t base = (size_t)(n0 + rr) * Keff + k0 + threadIdx.x;
        ob[base]          = h;
        ob[base + Kd]     = l;
        ob[base + 2 * Kd] = h;
    }
}

// ---------------- gather kernels ----------------
__global__ void k_leaf(const int* __restrict__ leaf_ids, const float4* __restrict__ emb) {
    int t = blockIdx.x * blockDim.x + threadIdx.x;
    if (t >= M * (D / 4)) return;
    int m = t >> 5, q = t & 31;
    ((float4*)g_hA)[t] = emb[leaf_ids[m] * 32 + q];
}

// gather concat -> split bf16 hi/lo into g_Xhi/g_Xlo (rows of 256)
__global__ void k_gather(int lv, const int* __restrict__ li, const int* __restrict__ ri, int hsel) {
    const int nrows = (lv < L) ? PADM : PADG;
    int t = blockIdx.x * blockDim.x + threadIdx.x;
    if (t >= nrows * 32) return;             // 256/8 groups per row
    int r = t >> 5, q = t & 31;
    const int* perm = (lv < L) ? (g_perm + lv * PADM) : g_permG;
    int node = perm[r];
    float v[8] = {0.f, 0.f, 0.f, 0.f, 0.f, 0.f, 0.f, 0.f};
    if (node >= 0) {
        const float* h = (hsel == 3) ? g_hA : g_hB;
        const float* src = (q < 16) ? (h + (size_t)li[node] * 128 + q * 8)
                                    : (h + (size_t)ri[node] * 128 + (q - 16) * 8);
        *(float4*)&v[0] = *(const float4*)src;
        *(float4*)&v[4] = *(const float4*)(src + 4);
    }
    __align__(16) __nv_bfloat16 hi8[8], lo8[8];
#pragma unroll
    for (int i = 0; i < 8; i++) {
        __nv_bfloat16 h = __float2bfloat16(v[i]);
        hi8[i] = h;
        lo8[i] = __float2bfloat16(v[i] - __bfloat162float(h));
    }
    *(uint4*)&g_Xhi[(size_t)r * 256 + q * 8] = *(uint4*)hi8;
    *(uint4*)&g_Xlo[(size_t)r * 256 + q * 8] = *(uint4*)lo8;
}

// ---------------- mma.sync bf16 grouped GEMM ----------------
// C[128 rows, 128 cols] = A''(bf16, K=3Kd) @ B''^T + bias, fid constant per row tile.
// 8 warps: wm = wid>>2 (2 x 64 rows), wn = wid&3 (4 x 32 cols).
// smem [row][k] padded stride 40 halves -> conflict-free LDS.32 fragment loads.
template <bool RELU, bool SCATTER>
__global__ __launch_bounds__(256, 2) void k_gemm_mma(
    int lv, int Acode, int Kd, int Nd, size_t woff,
    const float* __restrict__ bias_base, int Ccode, float* __restrict__ outbuf)
{
    const int fid = (lv < L) ? g_tilefid[lv * NTM + blockIdx.x] : g_tilefidG[blockIdx.x];
    if (fid < 0) return;

    const int Keff = 3 * Kd;
    const int ckps = Kd >> 5;        // 32-wide chunks per segment
    const int NC   = 3 * ckps;

    const __nv_bfloat16 *Ahi, *Alo;
    if (Acode == 0)      { Ahi = g_Xhi;  Alo = g_Xlo;  }
    else if (Acode == 1) { Ahi = g_Y1hi; Alo = g_Y1lo; }
    else                 { Ahi = g_Y2hi; Alo = g_Y2lo; }
    const __nv_bfloat16* __restrict__ Bt = g_Wt + woff + (size_t)fid * Nd * Keff;
    const float* __restrict__ bias = bias_base + (size_t)fid * Nd;

    const int rowBase = blockIdx.x * 128;
    const int colBase = blockIdx.y * 128;
    const int tid = threadIdx.x, lane = tid & 31, wid = tid >> 5;
    const int wm = wid >> 2, wn = wid & 3;
    const int gq = lane >> 2, tq = lane & 3;

    __shared__ __align__(16) unsigned short sA[2][128 * 40];
    __shared__ __align__(16) unsigned short sB[2][128 * 40];

    const int r  = tid >> 1;
    const int hf = tid & 1;

    float acc[4][4][4];
#pragma unroll
    for (int a = 0; a < 4; a++)
#pragma unroll
        for (int b = 0; b < 4; b++)
#pragma unroll
            for (int c = 0; c < 4; c++) acc[a][b][c] = 0.f;

    // prefetch chunk 0 (segment 0 = hi)
    uint4 pa0, pa1, pb0, pb1;
    {
        const __nv_bfloat16* Ap = Ahi + (size_t)(rowBase + r) * Kd + hf * 16;
        pa0 = *(const uint4*)Ap; pa1 = *(const uint4*)(Ap + 8);
        const __nv_bfloat16* Bp = Bt + (size_t)(colBase + r) * Keff + hf * 16;
        pb0 = *(const uint4*)Bp; pb1 = *(const uint4*)(Bp + 8);
    }

    for (int c = 0; c < NC; c++) {
        const int st = c & 1;
        *(uint4*)&sA[st][r * 40 + hf * 16]     = pa0;
        *(uint4*)&sA[st][r * 40 + hf * 16 + 8] = pa1;
        *(uint4*)&sB[st][r * 40 + hf * 16]     = pb0;
        *(uint4*)&sB[st][r * 40 + hf * 16 + 8] = pb1;
        __syncthreads();

        if (c + 1 < NC) {
            int cn   = c + 1;
            int segn = (cn >= 2 * ckps) ? 2 : (cn >= ckps ? 1 : 0);
            int ckn  = cn - segn * ckps;
            const __nv_bfloat16* Asrc = (segn < 2) ? Ahi : Alo;
            const __nv_bfloat16* Ap = Asrc + (size_t)(rowBase + r) * Kd + ckn * 32 + hf * 16;
            pa0 = *(const uint4*)Ap; pa1 = *(const uint4*)(Ap + 8);
            const __nv_bfloat16* Bp = Bt + (size_t)(colBase + r) * Keff + cn * 32 + hf * 16;
            pb0 = *(const uint4*)Bp; pb1 = *(const uint4*)(Bp + 8);
        }

        const unsigned short* As  = &sA[st][wm * 64 * 40];
        const unsigned short* Bsm = &sB[st][wn * 32 * 40];
#pragma unroll
        for (int kk = 0; kk < 32; kk += 16) {
            uint32_t bf[4][2];
#pragma unroll
            for (int nt = 0; nt < 4; nt++) {
                const unsigned short* bp = Bsm + (nt * 8 + gq) * 40 + kk + 2 * tq;
                bf[nt][0] = *(const uint32_t*)bp;
                bf[nt][1] = *(const uint32_t*)(bp + 8);
            }
#pragma unroll
            for (int mt = 0; mt < 4; mt++) {
                const unsigned short* ap = As + (mt * 16 + gq) * 40 + kk + 2 * tq;
                uint32_t a0 = *(const uint32_t*)ap;
                uint32_t a1 = *(const uint32_t*)(ap + 8 * 40);
                uint32_t a2 = *(const uint32_t*)(ap + 8);
                uint32_t a3 = *(const uint32_t*)(ap + 8 * 40 + 8);
#pragma unroll
                for (int nt = 0; nt < 4; nt++) {
                    asm volatile(
                        "mma.sync.aligned.m16n8k16.row.col.f32.bf16.bf16.f32 "
                        "{%0,%1,%2,%3}, {%4,%5,%6,%7}, {%8,%9}, {%0,%1,%2,%3};"
                        : "+f"(acc[mt][nt][0]), "+f"(acc[mt][nt][1]),
                          "+f"(acc[mt][nt][2]), "+f"(acc[mt][nt][3])
                        : "r"(a0), "r"(a1), "r"(a2), "r"(a3),
                          "r"(bf[nt][0]), "r"(bf[nt][1]));
                }
            }
        }
    }

    // ---- epilogue ----
    const int* perm = (lv < L) ? (g_perm + lv * PADM) : g_permG;

    if (SCATTER) {
        float* Cb;
        if (Ccode == 3)      Cb = g_hA;
        else if (Ccode == 4) Cb = g_hB;
        else                 Cb = outbuf;
#pragma unroll
        for (int mt = 0; mt < 4; mt++) {
#pragma unroll
            for (int hr = 0; hr < 2; hr++) {
                int row = rowBase + wm * 64 + mt * 16 + hr * 8 + gq;
                int dst = perm[row];
                if (dst < 0) continue;
#pragma unroll
                for (int nt = 0; nt < 4; nt++) {
                    int col = colBase + wn * 32 + nt * 8 + 2 * tq;
                    float2 v;
                    v.x = acc[mt][nt][hr * 2 + 0] + bias[col];
                    v.y = acc[mt][nt][hr * 2 + 1] + bias[col + 1];
                    if (RELU) { v.x = fmaxf(v.x, 0.f); v.y = fmaxf(v.y, 0.f); }
                    *(float2*)&Cb[(size_t)dst * Nd + col] = v;
                }
            }
        }
    } else {
        __nv_bfloat16 *Chi, *Clo;
        if (Ccode == 1) { Chi = g_Y1hi; Clo = g_Y1lo; }
        else            { Chi = g_Y2hi; Clo = g_Y2lo; }
#pragma unroll
        for (int mt = 0; mt < 4; mt++) {
#pragma unroll
            for (int hr = 0; hr < 2; hr++) {
                int row = rowBase + wm * 64 + mt * 16 + hr * 8 + gq;
#pragma unroll
                for (int nt = 0; nt < 4; nt++) {
                    int col = colBase + wn * 32 + nt * 8 + 2 * tq;
                    float vx = acc[mt][nt][hr * 2 + 0] + bias[col];
                    float vy = acc[mt][nt][hr * 2 + 1] + bias[col + 1];
                    if (RELU) { vx = fmaxf(vx, 0.f); vy = fmaxf(vy, 0.f); }
                    __nv_bfloat16 hx = __float2bfloat16(vx);
                    __nv_bfloat16 hy = __float2bfloat16(vy);
                    __nv_bfloat16 lx = __float2bfloat16(vx - __bfloat162float(hx));
                    __nv_bfloat16 ly = __float2bfloat16(vy - __bfloat162float(hy));
                    uint32_t hp = ((uint32_t)__bfloat16_as_ushort(hy) << 16) | __bfloat16_as_ushort(hx);
                    uint32_t lp = ((uint32_t)__bfloat16_as_ushort(ly) << 16) | __bfloat16_as_ushort(lx);
                    size_t o = (size_t)row * Nd + col;
                    *(uint32_t*)&Chi[o] = hp;
                    *(uint32_t*)&Clo[o] = lp;
                }
            }
        }
    }
}

// ---------------- launch ----------------
extern "C" void kernel_launch(void* const* d_in, const int* in_sizes, int n_in,
                              void* d_out, int out_size)
{
    const int*   leaf_ids = (const int*)d_in[0];
    const int*   left_idx = (const int*)d_in[1];
    const int*   right_idx= (const int*)d_in[2];
    const int*   nf_fid   = (const int*)d_in[3];
    const int*   gt_left  = (const int*)d_in[4];
    const int*   gt_right = (const int*)d_in[5];
    const int*   lf_fid   = (const int*)d_in[6];
    const float* emb      = (const float*)d_in[7];
    const float* W1 = (const float*)d_in[8];
    const float* b1 = (const float*)d_in[9];
    const float* W2 = (const float*)d_in[10];
    const float* b2 = (const float*)d_in[11];
    const float* W3 = (const float*)d_in[12];
    const float* b3 = (const float*)d_in[13];
    const float* Wl1= (const float*)d_in[14];
    const float* bl1= (const float*)d_in[15];
    const float* Wl2= (const float*)d_in[16];
    const float* bl2= (const float*)d_in[17];
    float* out = (float*)d_out;

    // weight transpose + bf16 split (every launch; deterministic)
    k_wconv<<<dim3(512/32, 256/32, 8), dim3(32, 8)>>>(W1,  OFF_W1,  256, 512);
    k_wconv<<<dim3(256/32, 512/32, 8), dim3(32, 8)>>>(W2,  OFF_W2,  512, 256);
    k_wconv<<<dim3(128/32, 256/32, 8), dim3(32, 8)>>>(W3,  OFF_W3,  256, 128);
    k_wconv<<<dim3(512/32, 256/32, 4), dim3(32, 8)>>>(Wl1, OFF_WL1, 256, 512);
    k_wconv<<<dim3(128/32, 512/32, 4), dim3(32, 8)>>>(Wl2, OFF_WL2, 512, 128);

    // group nodes by fid (device-side counting sort; output order-invariant)
    k_reset  <<<(L * PADM + 255) / 256, 256>>>();
    k_count  <<<(L * M + G + 255) / 256, 256>>>(nf_fid, lf_fid);
    k_scan   <<<1, 1>>>();
    k_scatter<<<(L * M + G + 255) / 256, 256>>>(nf_fid, lf_fid);

    // leaf embeddings -> g_hA (fp32)
    k_leaf<<<(M * (D / 4) + 255) / 256, 256>>>(leaf_ids, (const float4*)emb);

    int src = 3, dst = 4;  // 3 = g_hA, 4 = g_hB
    for (int l = 0; l < L; l++) {
        k_gather<<<(PADM * 32 + 255) / 256, 256>>>(l, left_idx + l * M, right_idx + l * M, src);
        dim3 g1(NTM, 4), g2(NTM, 2), g3(NTM, 1);
        k_gemm_mma<true,  false><<<g1, 256>>>(l, 0, 256, 512, OFF_W1, b1, 1, nullptr);
        k_gemm_mma<true,  false><<<g2, 256>>>(l, 1, 512, 256, OFF_W2, b2, 2, nullptr);
        k_gemm_mma<false, true ><<<g3, 256>>>(l, 2, 256, 128, OFF_W3, b3, dst, nullptr);
        int t = src; src = dst; dst = t;
    }

    // logic statements on final h (in buffer `src`)
    k_gather<<<(PADG * 32 + 255) / 256, 256>>>(L, gt_left, gt_right, src);
    dim3 gl1(NTG, 4), gl2(NTG, 1);
    k_gemm_mma<true,  false><<<gl1, 256>>>(L, 0, 256, 512, OFF_WL1, bl1, 1, nullptr);
    k_gemm_mma<false, true ><<<gl2, 256>>>(L, 1, 512, 128, OFF_WL2, bl2, 5, out);
}